// round 14
// baseline (speedup 1.0000x reference)
#include <cuda_runtime.h>

#define Hdim 128
#define PREP_BLOCKS 32
#define MAIN_BLOCKS 148
#define MAIN_THREADS 512
#define WARPS_PB (MAIN_THREADS / 32)
#define NWARP (MAIN_BLOCKS * WARPS_PB)

#define SLOTS 24            // ring slots per warp
#define SLOT_BYTES 544      // 512B row + 32B pad (conflict-free across groups)
#define D4 4                // pipeline depth in 4-row groups (16 rows in flight)
#define RING_BYTES_PW (SLOTS * SLOT_BYTES)
#define RING_BYTES (WARPS_PB * RING_BYTES_PW)
#define SMEM_DYN (RING_BYTES + 512)   // + su[128]

// scratch (no allocations allowed)
__device__ float g_u_part[PREP_BLOCKS][Hdim];
__device__ float g_c_part[PREP_BLOCKS];
__device__ double g_sum;
__device__ unsigned long long g_maxkey;
__device__ unsigned g_count;

__device__ __forceinline__ unsigned smem_u32(const void* p) {
    return (unsigned)__cvta_generic_to_shared(p);
}

// ---------------------------------------------------------------------------
// K1 (prep): 32 blocks x 128 threads (unchanged).
// ---------------------------------------------------------------------------
__global__ void __launch_bounds__(128) k_prep(const float* __restrict__ feat,
                                              const float* __restrict__ W1,
                                              const float* __restrict__ b1,
                                              const float* __restrict__ W2,
                                              const float* __restrict__ b2,
                                              const int*   __restrict__ prev)
{
    __shared__ float sphi[16];

    const int lane = threadIdx.x & 31;
    const int warp = threadIdx.x >> 5;
    const int j0   = blockIdx.x * 16;
    const int p    = prev[0];

    const float4 x = ((const float4*)(feat + (size_t)p * Hdim))[lane];

#pragma unroll
    for (int jj = 0; jj < 4; jj++) {
        const int j = j0 + warp * 4 + jj;
        const float4 w = ((const float4*)(W1 + (size_t)j * Hdim))[lane];
        float d = fmaf(w.x, x.x, fmaf(w.y, x.y, fmaf(w.z, x.z, w.w * x.w)));
        d += __shfl_xor_sync(0xffffffffu, d, 16);
        d += __shfl_xor_sync(0xffffffffu, d, 8);
        d += __shfl_xor_sync(0xffffffffu, d, 4);
        d += __shfl_xor_sync(0xffffffffu, d, 2);
        d += __shfl_xor_sync(0xffffffffu, d, 1);
        if (lane == 0) sphi[warp * 4 + jj] = d + b1[j];
    }
    __syncthreads();

    const int h = threadIdx.x;
    float acc = 0.0f;
#pragma unroll
    for (int jj = 0; jj < 16; jj++) {
        acc = fmaf(sphi[jj], W2[(size_t)(j0 + jj) * Hdim + h], acc);
    }
    g_u_part[blockIdx.x][h] = acc;

    if (threadIdx.x == 0) {
        float cp = 0.0f;
#pragma unroll
        for (int jj = 0; jj < 16; jj++) cp = fmaf(sphi[jj], b2[j0 + jj], cp);
        g_c_part[blockIdx.x] = cp;
        if (blockIdx.x == 0) { g_sum = 0.0; g_maxkey = 0ull; g_count = 0u; }
    }
}

// ---------------------------------------------------------------------------
// K2 (main): 148 blocks x 512 threads, 1 block/SM, 209KB dynamic smem.
// Per-warp cp.async ring: 24 slots x 544B; depth-4 groups of 4 rows
// (16 rows / 8KB in flight per warp, decoupled from registers).
// Consume: 8 lanes/row from smem, 3-stage butterfly, 4 parallel tanh/exp.
// ---------------------------------------------------------------------------
__global__ void __launch_bounds__(MAIN_THREADS, 1)
k_main(const float* __restrict__ feat,
       const float* __restrict__ adj,
       float* __restrict__ out,
       int N, int out_size)
{
    extern __shared__ char dsm[];
    float* su = (float*)(dsm + RING_BYTES);

    __shared__ float              sc;
    __shared__ float              ssum[WARPS_PB];
    __shared__ unsigned long long skey[WARPS_PB];

    const int lane  = threadIdx.x & 31;
    const int wwarp = threadIdx.x >> 5;
    const int gwarp = blockIdx.x * WARPS_PB + wwarp;

    char* ring = dsm + wwarp * RING_BYTES_PW;

    // balanced node range for this warp (<= 3 windows of 32)
    const int wstart = (int)((long long)gwarp * N / NWARP);
    const int wend   = (int)((long long)(gwarp + 1) * N / NWARP);

    int len0 = wend - wstart;          len0 = len0 > 32 ? 32 : len0;
    int len1 = wend - wstart - 32;     len1 = len1 < 0 ? 0 : (len1 > 32 ? 32 : len1);
    int len2 = wend - wstart - 64;     len2 = len2 < 0 ? 0 : (len2 > 32 ? 32 : len2);

    // adj loads issued before su reconstruction (overlap)
    const float a0 = (lane < len0) ? __ldg(adj + wstart + lane)      : 0.0f;
    const float a1 = (lane < len1) ? __ldg(adj + wstart + 32 + lane) : 0.0f;
    const float a2 = (lane < len2) ? __ldg(adj + wstart + 64 + lane) : 0.0f;

    // Reconstruct u
    if (threadIdx.x < Hdim) {
        float a = 0.0f;
#pragma unroll
        for (int pb = 0; pb < PREP_BLOCKS; pb++) a += g_u_part[pb][threadIdx.x];
        su[threadIdx.x] = a;
    }
    if (threadIdx.x == Hdim) {
        float a = 0.0f;
#pragma unroll
        for (int pb = 0; pb < PREP_BLOCKS; pb++) a += g_c_part[pb];
        sc = a;
    }
    __syncthreads();

    const int sub = lane & 7;    // float4 slot within row (0..7)
    const int grp = lane >> 3;   // which of 4 concurrent rows (0..3)

    // u float4s for this lane: indices sub, sub+8, sub+16, sub+24
    float4 ug[4];
#pragma unroll
    for (int t = 0; t < 4; t++) ug[t] = ((const float4*)su)[sub + 8 * t];
    const float cc = sc;

    const unsigned msk0 = __ballot_sync(0xffffffffu, a0 != 0.0f && lane < len0);
    const unsigned msk1 = __ballot_sync(0xffffffffu, a1 != 0.0f && lane < len1);
    const unsigned msk2 = __ballot_sync(0xffffffffu, a2 != 0.0f && lane < len2);
    const int m0 = __popc(msk0), m1 = __popc(msk1), m2 = __popc(msk2);
    const int mc0 = m0, mc1 = m0 + m1;
    const int M = m0 + m1 + m2;
    const int b0 = wstart, b1v = wstart + 32, b2v = wstart + 64;

    float lsum = 0.0f;
    unsigned long long lkey = 0ull;
    if (lane == 0)
        lsum += (float)((len0 - m0) + (len1 - m1) + (len2 - m2)); // exp(0) masked

    // ordinal k -> node id
    auto nodeOf = [&](int k) -> int {
        if (k < mc0) return b0  + (int)__fns(msk0, 0, k + 1);
        if (k < mc1) return b1v + (int)__fns(msk1, 0, k - mc0 + 1);
        return b2v + (int)__fns(msk2, 0, k - mc1 + 1);
    };

    const char* featb = (const char*)feat;
    const int G = (M + 3) >> 2;   // 4-row groups

    for (int g = 0; g < G + D4; g++) {
        // issue group g (4 rows, warp-collective: each lane copies 16B/row)
        if (g < G) {
#pragma unroll
            for (int q = 0; q < 4; q++) {
                const int k = 4 * g + q;
                if (k < M) {
                    const int node = nodeOf(k);
                    const unsigned dst = smem_u32(ring + (k % SLOTS) * SLOT_BYTES) + lane * 16;
                    const char* src = featb + (size_t)node * 512 + lane * 16;
                    asm volatile("cp.async.cg.shared.global [%0], [%1], 16;"
                                 :: "r"(dst), "l"(src));
                }
            }
        }
        asm volatile("cp.async.commit_group;");   // always (may be empty)

        // consume group g - D4
        if (g >= D4) {
            asm volatile("cp.async.wait_group %0;" :: "n"(D4));
            const int kc = 4 * (g - D4) + grp;
            float d = 0.0f;
            if (kc < M) {
                const char* sb = ring + (kc % SLOTS) * SLOT_BYTES + sub * 16;
                const float4 x0 = *(const float4*)(sb);
                const float4 x1 = *(const float4*)(sb + 128);
                const float4 x2 = *(const float4*)(sb + 256);
                const float4 x3 = *(const float4*)(sb + 384);
                float e0, e1;
                e0 = fmaf(ug[0].x, x0.x, fmaf(ug[0].y, x0.y,
                     fmaf(ug[0].z, x0.z, ug[0].w * x0.w)));
                e1 = fmaf(ug[1].x, x1.x, fmaf(ug[1].y, x1.y,
                     fmaf(ug[1].z, x1.z, ug[1].w * x1.w)));
                e0 = fmaf(ug[2].x, x2.x, fmaf(ug[2].y, x2.y,
                     fmaf(ug[2].z, x2.z, fmaf(ug[2].w, x2.w, e0))));
                e1 = fmaf(ug[3].x, x3.x, fmaf(ug[3].y, x3.y,
                     fmaf(ug[3].z, x3.z, fmaf(ug[3].w, x3.w, e1))));
                d = e0 + e1;
            }
            // 3-stage butterfly reduces all 4 rows (8-lane groups)
            d += __shfl_xor_sync(0xffffffffu, d, 4);
            d += __shfl_xor_sync(0xffffffffu, d, 2);
            d += __shfl_xor_sync(0xffffffffu, d, 1);

            if (sub == 0 && kc < M) {
                const int node   = nodeOf(kc);
                const float s    = (d + cc) * 0.04419417382415922f; // 1/sqrt(512)
                const float attn = 10.0f * tanhf(s);
                lsum += expf(attn);
                if (attn != 0.0f) {
                    const unsigned bu  = __float_as_uint(attn);
                    const unsigned enc = (bu & 0x80000000u) ? ~bu : (bu | 0x80000000u);
                    const unsigned long long key =
                        ((unsigned long long)enc << 32) |
                        (unsigned long long)(0xFFFFFFFFu - (unsigned)node);
                    if (key > lkey) lkey = key;
                }
            }
        }
    }

    // warp-level reduce of lsum / lkey
#pragma unroll
    for (int s = 16; s; s >>= 1) {
        lsum += __shfl_xor_sync(0xffffffffu, lsum, s);
        const unsigned long long o = __shfl_xor_sync(0xffffffffu, lkey, s);
        if (o > lkey) lkey = o;
    }

    if (lane == 0) { ssum[wwarp] = lsum; skey[wwarp] = lkey; }
    __syncthreads();

    if (threadIdx.x == 0) {
        float bs = 0.0f;
        unsigned long long bk = 0ull;
#pragma unroll
        for (int i = 0; i < WARPS_PB; i++) {
            bs += ssum[i];
            if (skey[i] > bk) bk = skey[i];
        }
        atomicAdd(&g_sum, (double)bs);
        atomicMax(&g_maxkey, bk);
        __threadfence();
        const unsigned done = atomicAdd(&g_count, 1u);
        if (done == MAIN_BLOCKS - 1u) {
            const double total = atomicAdd(&g_sum, 0.0);
            const unsigned long long k = atomicMax(&g_maxkey, 0ull);
            float pidx = 0.0f, pval = 0.0f;
            if (k != 0ull) {
                const unsigned enc = (unsigned)(k >> 32);
                const unsigned bb  = (enc & 0x80000000u) ? (enc ^ 0x80000000u) : ~enc;
                const float amax   = __uint_as_float(bb);
                const int   idx    = (int)(0xFFFFFFFFu - (unsigned)(k & 0xFFFFFFFFull));
                pidx = (float)idx;
                pval = (float)(exp((double)amax) / total);
            }
            out[0] = pidx;
            if (out_size > 1) out[1] = pval;
        }
    }
}

// ---------------------------------------------------------------------------
// inputs (metadata order): output[N,128], adj[N], W1[512,128], b1[512],
//                          W2[512,128], b2[512], prev_node (int scalar)
// ---------------------------------------------------------------------------
extern "C" void kernel_launch(void* const* d_in, const int* in_sizes, int n_in,
                              void* d_out, int out_size)
{
    const float* feat = (const float*)d_in[0];
    const float* adj  = (const float*)d_in[1];
    const float* W1   = (const float*)d_in[2];
    const float* b1   = (const float*)d_in[3];
    const float* W2   = (const float*)d_in[4];
    const float* b2   = (const float*)d_in[5];
    const int*   prev = (const int*)d_in[6];
    float* out = (float*)d_out;

    const int N = in_sizes[1];   // adj has N elements

    cudaFuncSetAttribute(k_main, cudaFuncAttributeMaxDynamicSharedMemorySize,
                         SMEM_DYN);

    k_prep<<<PREP_BLOCKS, 128>>>(feat, W1, b1, W2, b2, prev);
    k_main<<<MAIN_BLOCKS, MAIN_THREADS, SMEM_DYN>>>(feat, adj, out, N, out_size);
}

// round 15
// speedup vs baseline: 1.5389x; 1.5389x over previous
#include <cuda_runtime.h>

#define Hdim 128
#define PREP_BLOCKS 32
#define MAIN_BLOCKS 592
#define MAIN_THREADS 256
#define WARPS_PB (MAIN_THREADS / 32)
#define NWARP (MAIN_BLOCKS * WARPS_PB)

// scratch (no allocations allowed)
__device__ float g_u_part[PREP_BLOCKS][Hdim];
__device__ float g_c_part[PREP_BLOCKS];
__device__ double g_sum;
__device__ unsigned long long g_maxkey;
__device__ unsigned g_count;
__device__ unsigned g_prep_done;

struct f8 { float a0,a1,a2,a3,a4,a5,a6,a7; };

__device__ __forceinline__ f8 ldg8(const float* __restrict__ p) {
    f8 v;
    asm("ld.global.nc.v8.b32 {%0,%1,%2,%3,%4,%5,%6,%7}, [%8];"
        : "=f"(v.a0), "=f"(v.a1), "=f"(v.a2), "=f"(v.a3),
          "=f"(v.a4), "=f"(v.a5), "=f"(v.a6), "=f"(v.a7)
        : "l"(p));
    return v;
}

// ---------------------------------------------------------------------------
// Fused persistent kernel: 592 blocks x 256 threads, 4 blocks/SM (all
// resident -> spin is safe). Blocks 0-31 run prep; ALL warps issue their
// first chunk's adj + first 4-row feat batch BEFORE spinning on the prep
// flag, so prep latency is hidden under in-flight loads.
// Main loop = R12: 8 lanes/row, 4 rows/batch double-buffered, skip masked.
// ---------------------------------------------------------------------------
__global__ void __launch_bounds__(MAIN_THREADS, 4)
k_fused(const float* __restrict__ feat,
        const float* __restrict__ adj,
        const float* __restrict__ W1,
        const float* __restrict__ b1,
        const float* __restrict__ W2,
        const float* __restrict__ b2,
        const int*   __restrict__ prev,
        float* __restrict__ out,
        int N, int out_size)
{
    __shared__ float              sphi[16];
    __shared__ float              su[Hdim];
    __shared__ float              sc;
    __shared__ float              ssum[WARPS_PB];
    __shared__ unsigned long long skey[WARPS_PB];

    const int lane  = threadIdx.x & 31;
    const int wwarp = threadIdx.x >> 5;
    const int gwarp = blockIdx.x * WARPS_PB + wwarp;

    const int sub = lane & 7;    // 8-float slot within row (0..7)
    const int grp = lane >> 3;   // which of 4 concurrent rows (0..3)

    // ---- prep: blocks 0..31 compute 16 phi1 entries + u/c partials ----
    if (blockIdx.x < PREP_BLOCKS) {
        const int j0 = blockIdx.x * 16;
        if (threadIdx.x < 128) {
            const int p = prev[0];
            const float4 x = ((const float4*)(feat + (size_t)p * Hdim))[lane];
            const int pw = threadIdx.x >> 5;   // 0..3
#pragma unroll
            for (int jj = 0; jj < 4; jj++) {
                const int j = j0 + pw * 4 + jj;
                const float4 w = ((const float4*)(W1 + (size_t)j * Hdim))[lane];
                float d = fmaf(w.x, x.x, fmaf(w.y, x.y, fmaf(w.z, x.z, w.w * x.w)));
                d += __shfl_xor_sync(0xffffffffu, d, 16);
                d += __shfl_xor_sync(0xffffffffu, d, 8);
                d += __shfl_xor_sync(0xffffffffu, d, 4);
                d += __shfl_xor_sync(0xffffffffu, d, 2);
                d += __shfl_xor_sync(0xffffffffu, d, 1);
                if (lane == 0) sphi[pw * 4 + jj] = d + b1[j];
            }
        }
        __syncthreads();
        if (threadIdx.x < 128) {
            const int h = threadIdx.x;
            float acc = 0.0f;
#pragma unroll
            for (int jj = 0; jj < 16; jj++)
                acc = fmaf(sphi[jj], W2[(size_t)(j0 + jj) * Hdim + h], acc);
            g_u_part[blockIdx.x][h] = acc;
            if (h == 0) {
                float cp = 0.0f;
#pragma unroll
                for (int jj = 0; jj < 16; jj++) cp = fmaf(sphi[jj], b2[j0 + jj], cp);
                g_c_part[blockIdx.x] = cp;
                if (blockIdx.x == 0) { g_sum = 0.0; g_maxkey = 0ull; g_count = 0u; }
            }
        }
        __syncthreads();
        if (threadIdx.x == 0) {
            __threadfence();
            atomicAdd(&g_prep_done, 1u);
        }
    }

    // ---- pre-spin prefetch: first chunk's adj + first feat batch ----
    int base = gwarp * 32;
    float a_cur = 0.0f;
    if (base + lane < N) a_cur = __ldg(adj + base + lane);

    unsigned mask = __ballot_sync(0xffffffffu, a_cur != 0.0f);
    int m      = __popc(mask);
    int nvalid = (base < N) ? ((N - base >= 32) ? 32 : (N - base)) : 0;

    int rA = (int)__fns(mask, 0, grp + 1);
    f8 xA0, xA1;
    if (base < N && rA >= 0) {
        const float* row = feat + (size_t)(base + rA) * Hdim;
        xA0 = ldg8(row + sub * 8);
        xA1 = ldg8(row + (sub + 8) * 8);
    }

    // ---- spin until prep published (loads above remain in flight) ----
    if (threadIdx.x == 0) {
        while (atomicAdd(&g_prep_done, 0u) < PREP_BLOCKS) { }
    }
    __syncthreads();
    __threadfence();

    // ---- reconstruct u ----
    if (threadIdx.x < Hdim) {
        float a = 0.0f;
#pragma unroll
        for (int pb = 0; pb < PREP_BLOCKS; pb++) a += g_u_part[pb][threadIdx.x];
        su[threadIdx.x] = a;
    }
    if (threadIdx.x == Hdim) {
        float a = 0.0f;
#pragma unroll
        for (int pb = 0; pb < PREP_BLOCKS; pb++) a += g_c_part[pb];
        sc = a;
    }
    __syncthreads();

    float ureg[16];
#pragma unroll
    for (int q = 0; q < 8; q++) {
        ureg[q]     = su[sub * 8 + q];
        ureg[8 + q] = su[(sub + 8) * 8 + q];
    }
    const float cc = sc;

    float lsum = 0.0f;
    unsigned long long lkey = 0ull;

    // ---- main loop (loop-carried mask/rA/xA; first chunk pre-loaded) ----
    while (base < N) {
        // prefetch next chunk's adj
        const int basen = base + NWARP * 32;
        float a_next = 0.0f;
        if (basen < N && basen + lane < N) a_next = __ldg(adj + basen + lane);

        if (lane == 0) lsum += (float)(nvalid - m);   // exp(0) per masked node

        for (int j = 0; j < m; j += 4) {
            const int rB = (int)__fns(mask, 0, j + 4 + grp + 1);
            f8 xB0, xB1;
            if (rB >= 0) {
                const float* row = feat + (size_t)(base + rB) * Hdim;
                xB0 = ldg8(row + sub * 8);
                xB1 = ldg8(row + (sub + 8) * 8);
            }

            float d = 0.0f;
            if (rA >= 0) {
                float e0, e1;
                e0 = ureg[0] * xA0.a0;            e1 = ureg[1] * xA0.a1;
                e0 = fmaf(ureg[2],  xA0.a2, e0);  e1 = fmaf(ureg[3],  xA0.a3, e1);
                e0 = fmaf(ureg[4],  xA0.a4, e0);  e1 = fmaf(ureg[5],  xA0.a5, e1);
                e0 = fmaf(ureg[6],  xA0.a6, e0);  e1 = fmaf(ureg[7],  xA0.a7, e1);
                e0 = fmaf(ureg[8],  xA1.a0, e0);  e1 = fmaf(ureg[9],  xA1.a1, e1);
                e0 = fmaf(ureg[10], xA1.a2, e0);  e1 = fmaf(ureg[11], xA1.a3, e1);
                e0 = fmaf(ureg[12], xA1.a4, e0);  e1 = fmaf(ureg[13], xA1.a5, e1);
                e0 = fmaf(ureg[14], xA1.a6, e0);  e1 = fmaf(ureg[15], xA1.a7, e1);
                d = e0 + e1;
            }

            d += __shfl_xor_sync(0xffffffffu, d, 4);
            d += __shfl_xor_sync(0xffffffffu, d, 2);
            d += __shfl_xor_sync(0xffffffffu, d, 1);

            if (sub == 0 && rA >= 0) {
                const float s    = (d + cc) * 0.04419417382415922f; // 1/sqrt(512)
                const float attn = 10.0f * tanhf(s);
                lsum += expf(attn);
                if (attn != 0.0f) {
                    const unsigned n   = (unsigned)(base + rA);
                    const unsigned b   = __float_as_uint(attn);
                    const unsigned enc = (b & 0x80000000u) ? ~b : (b | 0x80000000u);
                    const unsigned long long key =
                        ((unsigned long long)enc << 32) |
                        (unsigned long long)(0xFFFFFFFFu - n);
                    if (key > lkey) lkey = key;
                }
            }
            rA  = rB;
            xA0 = xB0; xA1 = xB1;
        }

        // advance to next chunk; prefetch its first batch
        a_cur = a_next;
        base  = basen;
        if (base < N) {
            mask   = __ballot_sync(0xffffffffu, a_cur != 0.0f);
            m      = __popc(mask);
            nvalid = (N - base >= 32) ? 32 : (N - base);
            rA     = (int)__fns(mask, 0, grp + 1);
            if (rA >= 0) {
                const float* row = feat + (size_t)(base + rA) * Hdim;
                xA0 = ldg8(row + sub * 8);
                xA1 = ldg8(row + (sub + 8) * 8);
            }
        }
    }

    // ---- reductions + finalize ----
#pragma unroll
    for (int s = 16; s; s >>= 1) {
        lsum += __shfl_xor_sync(0xffffffffu, lsum, s);
        const unsigned long long o = __shfl_xor_sync(0xffffffffu, lkey, s);
        if (o > lkey) lkey = o;
    }

    if (lane == 0) { ssum[wwarp] = lsum; skey[wwarp] = lkey; }
    __syncthreads();

    if (threadIdx.x == 0) {
        float bs = 0.0f;
        unsigned long long bk = 0ull;
#pragma unroll
        for (int i = 0; i < WARPS_PB; i++) {
            bs += ssum[i];
            if (skey[i] > bk) bk = skey[i];
        }
        atomicAdd(&g_sum, (double)bs);
        atomicMax(&g_maxkey, bk);
        __threadfence();
        const unsigned done = atomicAdd(&g_count, 1u);
        if (done == MAIN_BLOCKS - 1u) {
            const double total = atomicAdd(&g_sum, 0.0);
            const unsigned long long k = atomicMax(&g_maxkey, 0ull);
            float pidx = 0.0f, pval = 0.0f;
            if (k != 0ull) {
                const unsigned enc = (unsigned)(k >> 32);
                const unsigned bb  = (enc & 0x80000000u) ? (enc ^ 0x80000000u) : ~enc;
                const float amax   = __uint_as_float(bb);
                const int   idx    = (int)(0xFFFFFFFFu - (unsigned)(k & 0xFFFFFFFFull));
                pidx = (float)idx;
                pval = (float)(exp((double)amax) / total);
            }
            out[0] = pidx;
            if (out_size > 1) out[1] = pval;
            g_prep_done = 0u;   // reset for next graph replay
        }
    }
}

// ---------------------------------------------------------------------------
// inputs (metadata order): output[N,128], adj[N], W1[512,128], b1[512],
//                          W2[512,128], b2[512], prev_node (int scalar)
// ---------------------------------------------------------------------------
extern "C" void kernel_launch(void* const* d_in, const int* in_sizes, int n_in,
                              void* d_out, int out_size)
{
    const float* feat = (const float*)d_in[0];
    const float* adj  = (const float*)d_in[1];
    const float* W1   = (const float*)d_in[2];
    const float* b1   = (const float*)d_in[3];
    const float* W2   = (const float*)d_in[4];
    const float* b2   = (const float*)d_in[5];
    const int*   prev = (const int*)d_in[6];
    float* out = (float*)d_out;

    const int N = in_sizes[1];   // adj has N elements

    k_fused<<<MAIN_BLOCKS, MAIN_THREADS>>>(feat, adj, W1, b1, W2, b2, prev,
                                           out, N, out_size);
}

// round 16
// speedup vs baseline: 1.7254x; 1.1212x over previous
#include <cuda_runtime.h>

#define Hdim 128
#define PREP_BLOCKS 32
#define MAIN_BLOCKS 592
#define MAIN_THREADS 256
#define WARPS_PB (MAIN_THREADS / 32)
#define NWARP (MAIN_BLOCKS * WARPS_PB)

// scratch (no allocations allowed)
__device__ float g_u_part[PREP_BLOCKS][Hdim];
__device__ float g_c_part[PREP_BLOCKS];
__device__ double g_sum;
__device__ unsigned long long g_maxkey;
__device__ unsigned g_count;

struct f8 { float a0,a1,a2,a3,a4,a5,a6,a7; };

__device__ __forceinline__ f8 ldg8(const float* __restrict__ p) {
    f8 v;
    asm("ld.global.nc.v8.b32 {%0,%1,%2,%3,%4,%5,%6,%7}, [%8];"
        : "=f"(v.a0), "=f"(v.a1), "=f"(v.a2), "=f"(v.a3),
          "=f"(v.a4), "=f"(v.a5), "=f"(v.a6), "=f"(v.a7)
        : "l"(p));
    return v;
}

// ---------------------------------------------------------------------------
// K1 (prep): 32 blocks x 128 threads. Triggers PDL completion as soon as its
// partials are globally visible.
// ---------------------------------------------------------------------------
__global__ void __launch_bounds__(128) k_prep(const float* __restrict__ feat,
                                              const float* __restrict__ W1,
                                              const float* __restrict__ b1,
                                              const float* __restrict__ W2,
                                              const float* __restrict__ b2,
                                              const int*   __restrict__ prev)
{
    __shared__ float sphi[16];

    const int lane = threadIdx.x & 31;
    const int warp = threadIdx.x >> 5;
    const int j0   = blockIdx.x * 16;
    const int p    = prev[0];

    const float4 x = ((const float4*)(feat + (size_t)p * Hdim))[lane];

#pragma unroll
    for (int jj = 0; jj < 4; jj++) {
        const int j = j0 + warp * 4 + jj;
        const float4 w = ((const float4*)(W1 + (size_t)j * Hdim))[lane];
        float d = fmaf(w.x, x.x, fmaf(w.y, x.y, fmaf(w.z, x.z, w.w * x.w)));
        d += __shfl_xor_sync(0xffffffffu, d, 16);
        d += __shfl_xor_sync(0xffffffffu, d, 8);
        d += __shfl_xor_sync(0xffffffffu, d, 4);
        d += __shfl_xor_sync(0xffffffffu, d, 2);
        d += __shfl_xor_sync(0xffffffffu, d, 1);
        if (lane == 0) sphi[warp * 4 + jj] = d + b1[j];
    }
    __syncthreads();

    const int h = threadIdx.x;
    float acc = 0.0f;
#pragma unroll
    for (int jj = 0; jj < 16; jj++) {
        acc = fmaf(sphi[jj], W2[(size_t)(j0 + jj) * Hdim + h], acc);
    }
    g_u_part[blockIdx.x][h] = acc;

    if (threadIdx.x == 0) {
        float cp = 0.0f;
#pragma unroll
        for (int jj = 0; jj < 16; jj++) cp = fmaf(sphi[jj], b2[j0 + jj], cp);
        g_c_part[blockIdx.x] = cp;
        if (blockIdx.x == 0) { g_sum = 0.0; g_maxkey = 0ull; g_count = 0u; }
    }

#if __CUDA_ARCH__ >= 900
    // results for this block are written; allow dependent launch to proceed
    cudaTriggerProgrammaticLaunchCompletion();
#endif
}

// ---------------------------------------------------------------------------
// K2 (main): R12 config — 592 blocks x 256 threads, 4 blocks/SM (32 warps/SM,
// regs<=64). PDL secondary: issues first chunk's adj + first feat batch,
// THEN cudaGridDependencySynchronize(), then reads prep partials.
// Main loop: 8 lanes/row, 4 rows/batch double-buffered, skip masked rows.
// ---------------------------------------------------------------------------
__global__ void __launch_bounds__(MAIN_THREADS, 4)
k_main(const float* __restrict__ feat,
       const float* __restrict__ adj,
       float* __restrict__ out,
       int N, int out_size)
{
    __shared__ float              su[Hdim];
    __shared__ float              sc;
    __shared__ float              ssum[WARPS_PB];
    __shared__ unsigned long long skey[WARPS_PB];

    const int lane  = threadIdx.x & 31;
    const int wwarp = threadIdx.x >> 5;
    const int gwarp = blockIdx.x * WARPS_PB + wwarp;

    const int sub = lane & 7;    // 8-float slot within row (0..7)
    const int grp = lane >> 3;   // which of 4 concurrent rows (0..3)

    // ---- pre-sync prefetch (independent of prep results) ----
    int base = gwarp * 32;
    float a_cur = 0.0f;
    if (base + lane < N) a_cur = __ldg(adj + base + lane);

    unsigned mask = __ballot_sync(0xffffffffu, a_cur != 0.0f);
    int m      = __popc(mask);
    int nvalid = (base < N) ? ((N - base >= 32) ? 32 : (N - base)) : 0;

    int rA = (int)__fns(mask, 0, grp + 1);
    f8 xA0, xA1;
    if (base < N && rA >= 0) {
        const float* row = feat + (size_t)(base + rA) * Hdim;
        xA0 = ldg8(row + sub * 8);
        xA1 = ldg8(row + (sub + 8) * 8);
    }

#if __CUDA_ARCH__ >= 900
    // wait for k_prep's results (loads above stay in flight)
    cudaGridDependencySynchronize();
#endif

    // ---- reconstruct u ----
    if (threadIdx.x < Hdim) {
        float a = 0.0f;
#pragma unroll
        for (int pb = 0; pb < PREP_BLOCKS; pb++) a += g_u_part[pb][threadIdx.x];
        su[threadIdx.x] = a;
    }
    if (threadIdx.x == Hdim) {
        float a = 0.0f;
#pragma unroll
        for (int pb = 0; pb < PREP_BLOCKS; pb++) a += g_c_part[pb];
        sc = a;
    }
    __syncthreads();

    float ureg[16];
#pragma unroll
    for (int q = 0; q < 8; q++) {
        ureg[q]     = su[sub * 8 + q];
        ureg[8 + q] = su[(sub + 8) * 8 + q];
    }
    const float cc = sc;

    float lsum = 0.0f;
    unsigned long long lkey = 0ull;

    // ---- main loop (loop-carried mask/rA/xA; first chunk pre-loaded) ----
    while (base < N) {
        // prefetch next chunk's adj
        const int basen = base + NWARP * 32;
        float a_next = 0.0f;
        if (basen < N && basen + lane < N) a_next = __ldg(adj + basen + lane);

        if (lane == 0) lsum += (float)(nvalid - m);   // exp(0) per masked node

        for (int j = 0; j < m; j += 4) {
            const int rB = (int)__fns(mask, 0, j + 4 + grp + 1);
            f8 xB0, xB1;
            if (rB >= 0) {
                const float* row = feat + (size_t)(base + rB) * Hdim;
                xB0 = ldg8(row + sub * 8);
                xB1 = ldg8(row + (sub + 8) * 8);
            }

            float d = 0.0f;
            if (rA >= 0) {
                float e0, e1;
                e0 = ureg[0] * xA0.a0;            e1 = ureg[1] * xA0.a1;
                e0 = fmaf(ureg[2],  xA0.a2, e0);  e1 = fmaf(ureg[3],  xA0.a3, e1);
                e0 = fmaf(ureg[4],  xA0.a4, e0);  e1 = fmaf(ureg[5],  xA0.a5, e1);
                e0 = fmaf(ureg[6],  xA0.a6, e0);  e1 = fmaf(ureg[7],  xA0.a7, e1);
                e0 = fmaf(ureg[8],  xA1.a0, e0);  e1 = fmaf(ureg[9],  xA1.a1, e1);
                e0 = fmaf(ureg[10], xA1.a2, e0);  e1 = fmaf(ureg[11], xA1.a3, e1);
                e0 = fmaf(ureg[12], xA1.a4, e0);  e1 = fmaf(ureg[13], xA1.a5, e1);
                e0 = fmaf(ureg[14], xA1.a6, e0);  e1 = fmaf(ureg[15], xA1.a7, e1);
                d = e0 + e1;
            }

            d += __shfl_xor_sync(0xffffffffu, d, 4);
            d += __shfl_xor_sync(0xffffffffu, d, 2);
            d += __shfl_xor_sync(0xffffffffu, d, 1);

            if (sub == 0 && rA >= 0) {
                const float s    = (d + cc) * 0.04419417382415922f; // 1/sqrt(512)
                const float attn = 10.0f * tanhf(s);
                lsum += expf(attn);
                if (attn != 0.0f) {
                    const unsigned n   = (unsigned)(base + rA);
                    const unsigned b   = __float_as_uint(attn);
                    const unsigned enc = (b & 0x80000000u) ? ~b : (b | 0x80000000u);
                    const unsigned long long key =
                        ((unsigned long long)enc << 32) |
                        (unsigned long long)(0xFFFFFFFFu - n);
                    if (key > lkey) lkey = key;
                }
            }
            rA  = rB;
            xA0 = xB0; xA1 = xB1;
        }

        // advance; prefetch next chunk's first batch
        a_cur = a_next;
        base  = basen;
        if (base < N) {
            mask   = __ballot_sync(0xffffffffu, a_cur != 0.0f);
            m      = __popc(mask);
            nvalid = (N - base >= 32) ? 32 : (N - base);
            rA     = (int)__fns(mask, 0, grp + 1);
            if (rA >= 0) {
                const float* row = feat + (size_t)(base + rA) * Hdim;
                xA0 = ldg8(row + sub * 8);
                xA1 = ldg8(row + (sub + 8) * 8);
            }
        }
    }

    // ---- reductions + finalize ----
#pragma unroll
    for (int s = 16; s; s >>= 1) {
        lsum += __shfl_xor_sync(0xffffffffu, lsum, s);
        const unsigned long long o = __shfl_xor_sync(0xffffffffu, lkey, s);
        if (o > lkey) lkey = o;
    }

    if (lane == 0) { ssum[wwarp] = lsum; skey[wwarp] = lkey; }
    __syncthreads();

    if (threadIdx.x == 0) {
        float bs = 0.0f;
        unsigned long long bk = 0ull;
#pragma unroll
        for (int i = 0; i < WARPS_PB; i++) {
            bs += ssum[i];
            if (skey[i] > bk) bk = skey[i];
        }
        atomicAdd(&g_sum, (double)bs);
        atomicMax(&g_maxkey, bk);
        __threadfence();
        const unsigned done = atomicAdd(&g_count, 1u);
        if (done == MAIN_BLOCKS - 1u) {
            const double total = atomicAdd(&g_sum, 0.0);
            const unsigned long long k = atomicMax(&g_maxkey, 0ull);
            float pidx = 0.0f, pval = 0.0f;
            if (k != 0ull) {
                const unsigned enc = (unsigned)(k >> 32);
                const unsigned bb  = (enc & 0x80000000u) ? (enc ^ 0x80000000u) : ~enc;
                const float amax   = __uint_as_float(bb);
                const int   idx    = (int)(0xFFFFFFFFu - (unsigned)(k & 0xFFFFFFFFull));
                pidx = (float)idx;
                pval = (float)(exp((double)amax) / total);
            }
            out[0] = pidx;
            if (out_size > 1) out[1] = pval;
        }
    }
}

// ---------------------------------------------------------------------------
// inputs (metadata order): output[N,128], adj[N], W1[512,128], b1[512],
//                          W2[512,128], b2[512], prev_node (int scalar)
// ---------------------------------------------------------------------------
extern "C" void kernel_launch(void* const* d_in, const int* in_sizes, int n_in,
                              void* d_out, int out_size)
{
    const float* feat = (const float*)d_in[0];
    const float* adj  = (const float*)d_in[1];
    const float* W1   = (const float*)d_in[2];
    const float* b1   = (const float*)d_in[3];
    const float* W2   = (const float*)d_in[4];
    const float* b2   = (const float*)d_in[5];
    const int*   prev = (const int*)d_in[6];
    float* out = (float*)d_out;

    const int N = in_sizes[1];   // adj has N elements

    k_prep<<<PREP_BLOCKS, 128>>>(feat, W1, b1, W2, b2, prev);

    // PDL: k_main may launch while k_prep is still running; it gates itself
    // with cudaGridDependencySynchronize() before touching prep results.
    cudaLaunchConfig_t cfg = {};
    cfg.gridDim  = dim3(MAIN_BLOCKS, 1, 1);
    cfg.blockDim = dim3(MAIN_THREADS, 1, 1);
    cudaLaunchAttribute attr[1];
    attr[0].id = cudaLaunchAttributeProgrammaticStreamSerialization;
    attr[0].val.programmaticStreamSerializationAllowed = 1;
    cfg.attrs    = attr;
    cfg.numAttrs = 1;
    cudaLaunchKernelEx(&cfg, k_main, feat, adj, out, N, out_size);
}